// round 11
// baseline (speedup 1.0000x reference)
#include <cuda_runtime.h>
#include <math.h>
#include <float.h>

#define BATCH 8
#define NPTS  4096
#define QPTS  1024
#define KNN   16

// ---------------- device scratch (no allocations allowed) ----------------
__device__ __align__(16) float g_coor  [BATCH*NPTS*3];
__device__ __align__(16) float g_f0    [BATCH*NPTS*8];
__device__ __align__(16) float g_f1    [BATCH*NPTS*32];
__device__ __align__(16) float g_f2    [BATCH*QPTS*64];
__device__ __align__(16) float g_f3    [BATCH*QPTS*64];
__device__ __align__(16) float g_fq1   [BATCH*QPTS*32];
__device__ __align__(16) float g_fq2   [BATCH*QPTS*64];
__device__ __align__(16) float g_coorq [BATCH*QPTS*3];
__device__ __align__(16) float g_nrm1  [BATCH*QPTS*3];
__device__ __align__(16) float g_pln1  [BATCH*QPTS];
__device__ __align__(16) float g_vmax  [BATCH*NPTS*32];
__device__ __align__(16) float g_vmin  [BATCH*NPTS*32];
__device__ __align__(16) float g_part  [BATCH*512*8];
__device__ __align__(16) float g_kd    [BATCH*NPTS*4*KNN];   // big enough for all stages
__device__ int   g_ki   [BATCH*NPTS*4*KNN];
__device__ int   g_knn  [BATCH*NPTS*KNN];
__device__ int   g_fps1 [BATCH*QPTS];
__device__ int   g_fps2 [BATCH*QPTS];
__device__ float g_mean [BATCH*4];
__device__ float g_rs   [BATCH*4];

// output layout: coor_q (B,1024,3) | f (B,1024,128) | normal_q (B,1024,3) | plane_q (B,1024,1)
#define OUT_COOR 0
#define OUT_F    (BATCH*QPTS*3)
#define OUT_NRM  (BATCH*QPTS*3 + BATCH*QPTS*128)
#define OUT_PLN  (BATCH*QPTS*3 + BATCH*QPTS*128 + BATCH*QPTS*3)

// ---------------- stage 0: split x, f0 = coor @ Win^T + bin ----------------
__global__ void init_kernel(const float* __restrict__ x,
                            const float* __restrict__ Win,
                            const float* __restrict__ bin,
                            float* __restrict__ coor, float* __restrict__ f0)
{
    int idx = blockIdx.x*blockDim.x + threadIdx.x;
    if (idx >= BATCH*NPTS) return;
    const float* xp = x + (size_t)idx*7;
    float cx = xp[0], cy = xp[1], cz = xp[2];
    coor[idx*3+0] = cx; coor[idx*3+1] = cy; coor[idx*3+2] = cz;
#pragma unroll
    for (int o = 0; o < 8; ++o) {
        float v = bin[o];
        v = fmaf(cx, Win[o*3+0], v);
        v = fmaf(cy, Win[o*3+1], v);
        v = fmaf(cz, Win[o*3+2], v);
        f0[idx*8+o] = v;
    }
}

// ---------------- kNN top-16 (smallest d2, ties -> lower index) ----------------
// Branchless insertion: all 16 steps read only OLD values -> no serial predicate
// chain. Semantics identical to sequential shift-insert with strict compares.
__device__ __forceinline__ void topk_insert(float (&hd)[KNN], int (&hi)[KNN],
                                            float d2, int idx)
{
    bool P[KNN];
#pragma unroll
    for (int s = 0; s < KNN; ++s) P[s] = (hd[s] > d2);
#pragma unroll
    for (int s = KNN-1; s >= 1; --s) {
        float nd = P[s] ? d2 : hd[s];
        int   ni = P[s] ? idx : hi[s];
        hd[s] = P[s-1] ? hd[s-1] : nd;
        hi[s] = P[s-1] ? hi[s-1] : ni;
    }
    if (P[0]) { hd[0] = d2; hi[0] = idx; }
}

// source-chunked kNN: each block handles one chunk of sources, exact per-chunk top-16
template<int CHUNK>
__global__ __launch_bounds__(256)
void knn_chunk_kernel(const float* __restrict__ cq, const float* __restrict__ ck,
                      int Q, int NSRC, float* __restrict__ outd, int* __restrict__ outi)
{
    constexpr int TILE = (CHUNK < 1024) ? CHUNK : 1024;
    __shared__ float4 tile[TILE];
    int b = blockIdx.y, ch = blockIdx.z, nch = gridDim.z;
    int q = blockIdx.x*256 + threadIdx.x;
    int base = ch*CHUNK;
    const float* qp = cq + ((size_t)b*Q + q)*3;
    float qx = qp[0], qy = qp[1], qz = qp[2];
    float qn = qx*qx + qy*qy + qz*qz;
    float hd[KNN]; int hi[KNN];
#pragma unroll
    for (int k = 0; k < KNN; ++k) { hd[k] = 3.4e38f; hi[k] = 0; }

#pragma unroll 1
    for (int t0 = base; t0 < base + CHUNK; t0 += TILE) {
        __syncthreads();
        for (int i = threadIdx.x; i < TILE; i += 256) {
            const float* p = ck + ((size_t)b*NSRC + t0 + i)*3;
            float px = p[0], py = p[1], pz = p[2];
            tile[i] = make_float4(px, py, pz, px*px + py*py + pz*pz);
        }
        __syncthreads();
#pragma unroll 4
        for (int j = 0; j < TILE; ++j) {
            float4 p = tile[j];
            float dot = fmaf(qz, p.z, fmaf(qy, p.y, qx*p.x));
            float d2  = (qn - 2.0f*dot) + p.w;
            if (d2 < hd[KNN-1]) topk_insert(hd, hi, d2, t0 + j);
        }
    }
    size_t o = ((size_t)(b*Q + q)*nch + ch)*KNN;
#pragma unroll
    for (int k = 0; k < KNN; ++k) { outd[o+k] = hd[k]; outi[o+k] = hi[k]; }
}

// exact stable NCH-way merge of per-chunk sorted top-16 lists -> global top-16
template<int NCH>
__global__ void knn_mergeN_kernel(const float* __restrict__ kd, const int* __restrict__ ki,
                                  int total, int* __restrict__ outidx)
{
    int t = blockIdx.x*256 + threadIdx.x;
    if (t >= total) return;
    const float* pd = kd + (size_t)t*NCH*KNN;
    const int*   pi = ki + (size_t)t*NCH*KNN;
    float h[NCH]; int hx[NCH]; int pp[NCH];
#pragma unroll
    for (int c = 0; c < NCH; ++c) { h[c] = pd[c*KNN]; hx[c] = pi[c*KNN]; pp[c] = 1; }
    const float INF = __int_as_float(0x7f800000);
    int* op = outidx + (size_t)t*KNN;
#pragma unroll
    for (int s = 0; s < KNN; ++s) {
        float bd = h[0]; int bi = hx[0]; int wc = 0;
#pragma unroll
        for (int c = 1; c < NCH; ++c) {
            if (h[c] < bd || (h[c] == bd && hx[c] < bi)) { bd = h[c]; bi = hx[c]; wc = c; }
        }
        op[s] = bi;
#pragma unroll
        for (int c = 0; c < NCH; ++c) {
            if (c == wc) {
                if (pp[c] < KNN) { h[c] = pd[c*KNN + pp[c]]; hx[c] = pi[c*KNN + pp[c]]; ++pp[c]; }
                else             { h[c] = INF; }
            }
        }
    }
}

// ---------------- farthest point sampling (exact argmax-first-tie) ----------------
template<int N, int THREADS>
__global__ __launch_bounds__(THREADS)
void fps_kernel(const float* __restrict__ coor, int* __restrict__ out)
{
    constexpr int P  = N / THREADS;
    constexpr int NW = THREADS / 32;
    int b = blockIdx.x, tid = threadIdx.x;
    int lane = tid & 31, w = tid >> 5;
    const float* cb = coor + (size_t)b*N*3;
    float px[P], py[P], pz[P], dist[P];
#pragma unroll
    for (int i = 0; i < P; ++i) {
        int p = tid*P + i;
        px[i] = cb[p*3+0]; py[i] = cb[p*3+1]; pz[i] = cb[p*3+2];
        dist[i] = __int_as_float(0x7f800000);   // +inf
    }
    __shared__ unsigned sD[2][NW]; __shared__ int sI[2][NW];
    __shared__ float sX[2][NW], sY[2][NW], sZ[2][NW];
    if (tid == 0) out[b*QPTS + 0] = 0;
    float cx = cb[0], cy = cb[1], cz = cb[2];

#pragma unroll 1
    for (int it = 1; it < QPTS; ++it) {
        int par = it & 1;
        float bd = -1.0f; int bi = 0;
        float bx = 0.f, by = 0.f, bz = 0.f;
#pragma unroll
        for (int i = 0; i < P; ++i) {
            float dx = px[i]-cx, dy = py[i]-cy, dz = pz[i]-cz;
            // match sum-over-last-axis order, no fma contraction
            float d = __fadd_rn(__fadd_rn(__fmul_rn(dx,dx), __fmul_rn(dy,dy)),
                                __fmul_rn(dz,dz));
            dist[i] = fminf(dist[i], d);
            if (dist[i] > bd) {                  // ascending i: first-max
                bd = dist[i]; bi = tid*P + i;
                bx = px[i]; by = py[i]; bz = pz[i];
            }
        }
        unsigned db   = __float_as_uint(bd);
        unsigned wmax = __reduce_max_sync(0xffffffffu, db);
        unsigned msk  = __ballot_sync(0xffffffffu, db == wmax);
        int src = __ffs(msk) - 1;                // lowest lane = lowest index
        if (lane == src) {
            sD[par][w] = wmax; sI[par][w] = bi;
            sX[par][w] = bx;   sY[par][w] = by;  sZ[par][w] = bz;
        }
        __syncthreads();
        unsigned slotd = sD[par][lane & (NW-1)];
        unsigned gmax = __reduce_max_sync(0xffffffffu, slotd);
        unsigned m2   = __ballot_sync(0xffffffffu, slotd == gmax);
        int w2 = __ffs(m2) - 1;                  // lowest warp = lowest index
        if (tid == 0) out[b*QPTS + it] = sI[par][w2];
        cx = sX[par][w2]; cy = sY[par][w2]; cz = sZ[par][w2];   // LDS broadcast
    }
}

// ---------------- fused edge-conv: packed f32x2 GEMM + max/min + GN partials ----------
template<int C, int CO>
__global__ __launch_bounds__(256)
void conv_kernel(const float* __restrict__ fsrc, const float* __restrict__ fq,
                 const int* __restrict__ knnidx, const float* __restrict__ W,
                 float* __restrict__ vmax, float* __restrict__ vmin,
                 float* __restrict__ part, int Q, int NSRC)
{
    constexpr int C2 = 2*C, CT = CO/16, CT2 = CT/2, NCH = C2/16;
    extern __shared__ float smem[];
    int*   sNb  = (int*)smem;
    float* sFq  = smem + 128;
    float* sNbF = sFq + 8*C;
    float* sW   = sNbF + 128*C;

    int b = blockIdx.y, blk = blockIdx.x, qbase = blk*8;
    int tid = threadIdx.x;
    int ty = tid >> 4, tx = tid & 15;
    int lane = tid & 31, w = tid >> 5;

    if (tid < 128) sNb[tid] = knnidx[((size_t)(b*Q + qbase))*KNN + tid];
    for (int e = tid; e < 8*C; e += 256) {
        int r = e / C, c = e % C;
        sFq[e] = fq[((size_t)(b*Q + qbase + r))*C + c];
    }
    __syncthreads();
    for (int v = tid; v < 128*(C/4); v += 256) {
        int row = v / (C/4), c4 = v % (C/4);
        float4 t = *reinterpret_cast<const float4*>(
            fsrc + ((size_t)(b*NSRC) + sNb[row])*C + c4*4);
        float* d = sNbF + row*C + c4*4;
        d[0] = t.x; d[1] = t.y; d[2] = t.z; d[3] = t.w;
    }
    unsigned long long acc2[8][CT2];
#pragma unroll
    for (int r = 0; r < 8; ++r)
#pragma unroll
        for (int i = 0; i < CT2; ++i) acc2[r][i] = 0ull;
    __syncthreads();

#pragma unroll 1
    for (int ch = 0; ch < NCH; ++ch) {
        for (int e = tid; e < 16*CO; e += 256) {
            int o = e % CO, j = e / CO;
            sW[j*CO + o] = W[(size_t)o*C2 + ch*16 + j];
        }
        __syncthreads();
#pragma unroll
        for (int j = 0; j < 16; ++j) {
            int c2 = ch*16 + j;
            unsigned long long wp[CT2];
            const unsigned long long* ws =
                reinterpret_cast<const unsigned long long*>(sW + j*CO + tx*CT);
#pragma unroll
            for (int i = 0; i < CT2; ++i) wp[i] = ws[i];
#pragma unroll
            for (int r = 0; r < 8; ++r) {
                int row = ty*8 + r, ql = row >> 4;
                float ev = (c2 < C) ? (sNbF[row*C + c2] - sFq[ql*C + c2])
                                    : sFq[ql*C + (c2 - C)];
                unsigned long long evev;
                asm("mov.b64 %0, {%1, %1};" : "=l"(evev) : "f"(ev));
#pragma unroll
                for (int i = 0; i < CT2; ++i)
                    asm("fma.rn.f32x2 %0, %1, %2, %0;"
                        : "+l"(acc2[r][i]) : "l"(evev), "l"(wp[i]));
            }
        }
        __syncthreads();
    }

    // phase 2 (registers): max/min over this thread's 8 rows per channel pair,
    // combine ty-pair via shfl_xor(16) -> full 16-k reduction for query w.
    int khalf = ty & 1;
    float s = 0.0f, ss = 0.0f;
    size_t obase = ((size_t)(b*Q + qbase + w))*CO + tx*CT;
#pragma unroll
    for (int i2 = 0; i2 < CT2; ++i2) {
        float mx0 = -3.4e38f, mn0 = 3.4e38f, mx1 = -3.4e38f, mn1 = 3.4e38f;
#pragma unroll
        for (int r = 0; r < 8; ++r) {
            unsigned long long a = acc2[r][i2];
            float v0 = __uint_as_float((unsigned)a);
            float v1 = __uint_as_float((unsigned)(a >> 32));
            mx0 = fmaxf(mx0, v0); mn0 = fminf(mn0, v0);
            mx1 = fmaxf(mx1, v1); mn1 = fminf(mn1, v1);
            s += v0; ss = fmaf(v0, v0, ss);
            s += v1; ss = fmaf(v1, v1, ss);
        }
        mx0 = fmaxf(mx0, __shfl_xor_sync(0xffffffffu, mx0, 16));
        mn0 = fminf(mn0, __shfl_xor_sync(0xffffffffu, mn0, 16));
        mx1 = fmaxf(mx1, __shfl_xor_sync(0xffffffffu, mx1, 16));
        mn1 = fminf(mn1, __shfl_xor_sync(0xffffffffu, mn1, 16));
        if (khalf == 0) {
            vmax[obase + 2*i2]   = mx0; vmin[obase + 2*i2]   = mn0;
            vmax[obase + 2*i2+1] = mx1; vmin[obase + 2*i2+1] = mn1;
        }
    }
    // segmented group sums: group g = tx>>2 ; combine ty pair + tx quad
    s  += __shfl_xor_sync(0xffffffffu, s, 16);
    ss += __shfl_xor_sync(0xffffffffu, ss, 16);
    s  += __shfl_xor_sync(0xffffffffu, s, 1);
    ss += __shfl_xor_sync(0xffffffffu, ss, 1);
    s  += __shfl_xor_sync(0xffffffffu, s, 2);
    ss += __shfl_xor_sync(0xffffffffu, ss, 2);
    float* sGs  = smem;        // safe: barrier above, phase-1 buffers dead
    float* sGss = smem + 32;
    if ((lane & 16) == 0 && (lane & 3) == 0) {
        int slot = w*4 + (lane >> 2);
        sGs[slot] = s; sGss[slot] = ss;
    }
    __syncthreads();
    if (tid < 4) {
        float gs = 0.0f, gss = 0.0f;
#pragma unroll
        for (int ww = 0; ww < 8; ++ww) { gs += sGs[ww*4 + tid]; gss += sGss[ww*4 + tid]; }
        float* p = part + ((size_t)b*gridDim.x + blk)*8;
        p[tid*2] = gs; p[tid*2+1] = gss;
    }
}

// ---------------- GN statistics (deterministic fixed-order) ----------------
__global__ void stats_kernel(const float* __restrict__ part, int NB, float invcnt,
                             float* __restrict__ mean, float* __restrict__ rs)
{
    int bg = blockIdx.x;            // b*4+g
    int b = bg >> 2, g = bg & 3;
    float s = 0.0f, ss = 0.0f;
    for (int i = threadIdx.x; i < NB; i += 32) {
        const float* p = part + ((size_t)b*NB + i)*8 + g*2;
        s += p[0]; ss += p[1];
    }
#pragma unroll
    for (int off = 16; off; off >>= 1) {
        s  += __shfl_down_sync(0xffffffffu, s,  off);
        ss += __shfl_down_sync(0xffffffffu, ss, off);
    }
    if (threadIdx.x == 0) {
        float m = s * invcnt;
        float var = ss * invcnt - m*m;
        mean[bg] = m;
        rs[bg] = 1.0f / sqrtf(var + 1e-5f);
    }
}

// ---------------- apply GN + affine + LeakyReLU on the extremum ----------------
__global__ void apply_kernel(const float* __restrict__ vmax, const float* __restrict__ vmin,
                             const float* __restrict__ mean, const float* __restrict__ rs,
                             const float* __restrict__ gw, const float* __restrict__ gb,
                             float* __restrict__ dst, int Q, int CO)
{
    int idx = blockIdx.x*256 + threadIdx.x;
    if (idx >= BATCH*Q*CO) return;
    int c = idx % CO;
    int b = idx / (Q*CO);
    int g = c / (CO >> 2);
    float gwc = gw[c];
    float v = (gwc >= 0.0f) ? vmax[idx] : vmin[idx];
    float y = fmaf((v - mean[b*4+g]) * rs[b*4+g], gwc, gb[c]);
    dst[idx] = (y > 0.0f) ? y : 0.2f*y;
}

// ---------------- gathers ----------------
__global__ void gather1_kernel(const float* __restrict__ x, const float* __restrict__ f1,
                               const int* __restrict__ idx,
                               float* __restrict__ coorq, float* __restrict__ nrm,
                               float* __restrict__ pln, float* __restrict__ fq)
{
    int t = blockIdx.x*256 + threadIdx.x;
    if (t >= BATCH*QPTS) return;
    int b = t >> 10;
    int i = idx[t];
    const float* xs = x + ((size_t)b*NPTS + i)*7;
    coorq[t*3+0] = xs[0]; coorq[t*3+1] = xs[1]; coorq[t*3+2] = xs[2];
    nrm[t*3+0] = xs[3]; nrm[t*3+1] = xs[4]; nrm[t*3+2] = xs[5];
    pln[t] = xs[6];
    const float4* fs = (const float4*)(f1 + ((size_t)b*NPTS + i)*32);
    float4* fd = (float4*)(fq + (size_t)t*32);
#pragma unroll
    for (int j = 0; j < 8; ++j) fd[j] = fs[j];
}

__global__ void gather2_kernel(const float* __restrict__ coorq, const float* __restrict__ nrm1,
                               const float* __restrict__ pln1, const float* __restrict__ f3,
                               const int* __restrict__ idx,
                               float* __restrict__ out, float* __restrict__ fq2)
{
    int t = blockIdx.x*256 + threadIdx.x;
    if (t >= BATCH*QPTS) return;
    int b = t >> 10;
    int i = idx[t];
    size_t src = (size_t)b*QPTS + i;
    out[OUT_COOR + t*3+0] = coorq[src*3+0];
    out[OUT_COOR + t*3+1] = coorq[src*3+1];
    out[OUT_COOR + t*3+2] = coorq[src*3+2];
    out[OUT_NRM + t*3+0] = nrm1[src*3+0];
    out[OUT_NRM + t*3+1] = nrm1[src*3+1];
    out[OUT_NRM + t*3+2] = nrm1[src*3+2];
    out[OUT_PLN + t] = pln1[src];
    const float4* fs = (const float4*)(f3 + src*64);
    float4* fd = (float4*)(fq2 + (size_t)t*64);
#pragma unroll
    for (int j = 0; j < 16; ++j) fd[j] = fs[j];
}

// ---------------- host ----------------
static int conv_smem(int C, int CO) {
    return 4 * (128 + 8*C + 128*C + 16*CO);
}

static cudaStream_t s_side = 0;
static cudaEvent_t  s_evF1, s_evJ1, s_evF2, s_evJ2;

extern "C" void kernel_launch(void* const* d_in, const int* in_sizes, int n_in,
                              void* d_out, int out_size)
{
    const float* x   = (const float*)d_in[0];
    const float* Win = (const float*)d_in[1];
    const float* bin = (const float*)d_in[2];
    const float* W1  = (const float*)d_in[3];
    const float* g1w = (const float*)d_in[4];
    const float* g1b = (const float*)d_in[5];
    const float* W2  = (const float*)d_in[6];
    const float* g2w = (const float*)d_in[7];
    const float* g2b = (const float*)d_in[8];
    const float* W3  = (const float*)d_in[9];
    const float* g3w = (const float*)d_in[10];
    const float* g3b = (const float*)d_in[11];
    const float* W4  = (const float*)d_in[12];
    const float* g4w = (const float*)d_in[13];
    const float* g4b = (const float*)d_in[14];
    float* out = (float*)d_out;

    if (!s_side) {
        cudaStreamCreateWithFlags(&s_side, cudaStreamNonBlocking);
        cudaEventCreateWithFlags(&s_evF1, cudaEventDisableTiming);
        cudaEventCreateWithFlags(&s_evJ1, cudaEventDisableTiming);
        cudaEventCreateWithFlags(&s_evF2, cudaEventDisableTiming);
        cudaEventCreateWithFlags(&s_evJ2, cudaEventDisableTiming);
    }

    float *coor, *f0, *f1, *f2, *f3, *fq1, *fq2, *coorq, *nrm1, *pln1;
    float *vmax, *vmin, *part, *mean, *rs, *kd;
    int *knn, *fps1, *fps2, *ki;
    cudaGetSymbolAddress((void**)&coor,  g_coor);
    cudaGetSymbolAddress((void**)&f0,    g_f0);
    cudaGetSymbolAddress((void**)&f1,    g_f1);
    cudaGetSymbolAddress((void**)&f2,    g_f2);
    cudaGetSymbolAddress((void**)&f3,    g_f3);
    cudaGetSymbolAddress((void**)&fq1,   g_fq1);
    cudaGetSymbolAddress((void**)&fq2,   g_fq2);
    cudaGetSymbolAddress((void**)&coorq, g_coorq);
    cudaGetSymbolAddress((void**)&nrm1,  g_nrm1);
    cudaGetSymbolAddress((void**)&pln1,  g_pln1);
    cudaGetSymbolAddress((void**)&vmax,  g_vmax);
    cudaGetSymbolAddress((void**)&vmin,  g_vmin);
    cudaGetSymbolAddress((void**)&part,  g_part);
    cudaGetSymbolAddress((void**)&mean,  g_mean);
    cudaGetSymbolAddress((void**)&rs,    g_rs);
    cudaGetSymbolAddress((void**)&kd,    g_kd);
    cudaGetSymbolAddress((void**)&ki,    g_ki);
    cudaGetSymbolAddress((void**)&knn,   g_knn);
    cudaGetSymbolAddress((void**)&fps1,  g_fps1);
    cudaGetSymbolAddress((void**)&fps2,  g_fps2);

    cudaFuncSetAttribute(conv_kernel<8,32>,   cudaFuncAttributeMaxDynamicSharedMemorySize, conv_smem(8,32));
    cudaFuncSetAttribute(conv_kernel<32,64>,  cudaFuncAttributeMaxDynamicSharedMemorySize, conv_smem(32,64));
    cudaFuncSetAttribute(conv_kernel<64,64>,  cudaFuncAttributeMaxDynamicSharedMemorySize, conv_smem(64,64));
    cudaFuncSetAttribute(conv_kernel<64,128>, cudaFuncAttributeMaxDynamicSharedMemorySize, conv_smem(64,128));

    // stage 0
    init_kernel<<<(BATCH*NPTS+255)/256, 256>>>(x, Win, bin, coor, f0);

    // fork: FPS level 1 on side stream (only needs coor; 8 blocks, near-free overlap)
    cudaEventRecord(s_evF1, 0);
    cudaStreamWaitEvent(s_side, s_evF1, 0);
    fps_kernel<NPTS,1024><<<BATCH, 1024, 0, s_side>>>(coor, fps1);
    cudaEventRecord(s_evJ1, s_side);

    // stage 1 (overlaps FPS1): chunked knn(4096 vs 4096), conv C=8 CO=32
    knn_chunk_kernel<1024><<<dim3(NPTS/256, BATCH, 4), 256>>>(coor, coor, NPTS, NPTS, kd, ki);
    knn_mergeN_kernel<4><<<(BATCH*NPTS+255)/256, 256>>>(kd, ki, BATCH*NPTS, knn);
    conv_kernel<8,32><<<dim3(NPTS/8, BATCH), 256, conv_smem(8,32)>>>(
        f0, f0, knn, W1, vmax, vmin, part, NPTS, NPTS);
    stats_kernel<<<BATCH*4, 32>>>(part, NPTS/8, 1.0f/(NPTS*16*8), mean, rs);
    apply_kernel<<<(BATCH*NPTS*32+255)/256, 256>>>(vmax, vmin, mean, rs, g1w, g1b, f1, NPTS, 32);

    // join FPS1, gather
    cudaStreamWaitEvent(0, s_evJ1, 0);
    gather1_kernel<<<(BATCH*QPTS+255)/256, 256>>>(x, f1, fps1, coorq, nrm1, pln1, fq1);

    // fork: FPS level 2 on side stream (only needs coorq)
    cudaEventRecord(s_evF2, 0);
    cudaStreamWaitEvent(s_side, s_evF2, 0);
    fps_kernel<QPTS,256><<<BATCH, 256, 0, s_side>>>(coorq, fps2);
    cudaEventRecord(s_evJ2, s_side);

    // stage 2 (overlaps FPS2): 8-chunk knn(1024 q vs 4096 src), conv C=32 CO=64
    knn_chunk_kernel<512><<<dim3(QPTS/256, BATCH, 8), 256>>>(coorq, coor, QPTS, NPTS, kd, ki);
    knn_mergeN_kernel<8><<<(BATCH*QPTS+255)/256, 256>>>(kd, ki, BATCH*QPTS, knn);
    conv_kernel<32,64><<<dim3(QPTS/8, BATCH), 256, conv_smem(32,64)>>>(
        f1, fq1, knn, W2, vmax, vmin, part, QPTS, NPTS);
    stats_kernel<<<BATCH*4, 32>>>(part, QPTS/8, 1.0f/(QPTS*16*16), mean, rs);
    apply_kernel<<<(BATCH*QPTS*64+255)/256, 256>>>(vmax, vmin, mean, rs, g2w, g2b, f2, QPTS, 64);

    // stage 3 (overlaps FPS2): 4-chunk knn(1024 vs 1024), conv C=64 CO=64
    knn_chunk_kernel<256><<<dim3(QPTS/256, BATCH, 4), 256>>>(coorq, coorq, QPTS, QPTS, kd, ki);
    knn_mergeN_kernel<4><<<(BATCH*QPTS+255)/256, 256>>>(kd, ki, BATCH*QPTS, knn);
    conv_kernel<64,64><<<dim3(QPTS/8, BATCH), 256, conv_smem(64,64)>>>(
        f2, f2, knn, W3, vmax, vmin, part, QPTS, QPTS);
    stats_kernel<<<BATCH*4, 32>>>(part, QPTS/8, 1.0f/(QPTS*16*16), mean, rs);
    apply_kernel<<<(BATCH*QPTS*64+255)/256, 256>>>(vmax, vmin, mean, rs, g3w, g3b, f3, QPTS, 64);

    // join FPS2, gather (writes coor_q/normal_q/plane_q straight to output)
    cudaStreamWaitEvent(0, s_evJ2, 0);
    gather2_kernel<<<(BATCH*QPTS+255)/256, 256>>>(coorq, nrm1, pln1, f3, fps2, out, fq2);

    // stage 4: 4-chunk knn(permuted 1024 vs 1024), conv C=64 CO=128 -> final f into output
    knn_chunk_kernel<256><<<dim3(QPTS/256, BATCH, 4), 256>>>(out + OUT_COOR, coorq, QPTS, QPTS, kd, ki);
    knn_mergeN_kernel<4><<<(BATCH*QPTS+255)/256, 256>>>(kd, ki, BATCH*QPTS, knn);
    conv_kernel<64,128><<<dim3(QPTS/8, BATCH), 256, conv_smem(64,128)>>>(
        f3, fq2, knn, W4, vmax, vmin, part, QPTS, QPTS);
    stats_kernel<<<BATCH*4, 32>>>(part, QPTS/8, 1.0f/(QPTS*16*32), mean, rs);
    apply_kernel<<<(BATCH*QPTS*128+255)/256, 256>>>(vmax, vmin, mean, rs, g4w, g4b,
                                                    out + OUT_F, QPTS, 128);
}

// round 12
// speedup vs baseline: 1.0814x; 1.0814x over previous
#include <cuda_runtime.h>
#include <math.h>
#include <float.h>

#define BATCH 8
#define NPTS  4096
#define QPTS  1024
#define KNN   16

// ---------------- device scratch (no allocations allowed) ----------------
__device__ __align__(16) float g_coor  [BATCH*NPTS*3];
__device__ __align__(16) float g_f0    [BATCH*NPTS*8];
__device__ __align__(16) float g_f1    [BATCH*NPTS*32];
__device__ __align__(16) float g_f2    [BATCH*QPTS*64];
__device__ __align__(16) float g_f3    [BATCH*QPTS*64];
__device__ __align__(16) float g_fq1   [BATCH*QPTS*32];
__device__ __align__(16) float g_fq2   [BATCH*QPTS*64];
__device__ __align__(16) float g_coorq [BATCH*QPTS*3];
__device__ __align__(16) float g_nrm1  [BATCH*QPTS*3];
__device__ __align__(16) float g_pln1  [BATCH*QPTS];
__device__ __align__(16) float g_vmax  [BATCH*NPTS*32];
__device__ __align__(16) float g_vmin  [BATCH*NPTS*32];
__device__ __align__(16) float g_part  [BATCH*512*8];
__device__ __align__(16) float g_kd    [BATCH*QPTS*4*KNN];
__device__ int   g_ki   [BATCH*QPTS*4*KNN];
__device__ int   g_knn  [BATCH*NPTS*KNN];
__device__ int   g_fps1 [BATCH*QPTS];
__device__ int   g_fps2 [BATCH*QPTS];
__device__ float g_mean [BATCH*4];
__device__ float g_rs   [BATCH*4];

// output layout: coor_q (B,1024,3) | f (B,1024,128) | normal_q (B,1024,3) | plane_q (B,1024,1)
#define OUT_COOR 0
#define OUT_F    (BATCH*QPTS*3)
#define OUT_NRM  (BATCH*QPTS*3 + BATCH*QPTS*128)
#define OUT_PLN  (BATCH*QPTS*3 + BATCH*QPTS*128 + BATCH*QPTS*3)

// ---------------- packed f32x2 helpers ----------------
__device__ __forceinline__ unsigned long long pk2(float a, float b) {
    unsigned long long r; asm("mov.b64 %0, {%1, %2};" : "=l"(r) : "f"(a), "f"(b)); return r;
}
__device__ __forceinline__ float lo2(unsigned long long v) { return __uint_as_float((unsigned)v); }
__device__ __forceinline__ float hi2(unsigned long long v) { return __uint_as_float((unsigned)(v >> 32)); }
__device__ __forceinline__ unsigned long long add2p(unsigned long long a, unsigned long long b) {
    unsigned long long r; asm("add.rn.f32x2 %0, %1, %2;" : "=l"(r) : "l"(a), "l"(b)); return r;
}
__device__ __forceinline__ unsigned long long mul2p(unsigned long long a, unsigned long long b) {
    unsigned long long r; asm("mul.rn.f32x2 %0, %1, %2;" : "=l"(r) : "l"(a), "l"(b)); return r;
}

// ---------------- stage 0: split x, f0 = coor @ Win^T + bin ----------------
__global__ void init_kernel(const float* __restrict__ x,
                            const float* __restrict__ Win,
                            const float* __restrict__ bin,
                            float* __restrict__ coor, float* __restrict__ f0)
{
    int idx = blockIdx.x*blockDim.x + threadIdx.x;
    if (idx >= BATCH*NPTS) return;
    const float* xp = x + (size_t)idx*7;
    float cx = xp[0], cy = xp[1], cz = xp[2];
    coor[idx*3+0] = cx; coor[idx*3+1] = cy; coor[idx*3+2] = cz;
#pragma unroll
    for (int o = 0; o < 8; ++o) {
        float v = bin[o];
        v = fmaf(cx, Win[o*3+0], v);
        v = fmaf(cy, Win[o*3+1], v);
        v = fmaf(cz, Win[o*3+2], v);
        f0[idx*8+o] = v;
    }
}

// ---------------- kNN top-16 (smallest d2, ties -> lower index) ----------------
// Branchless insertion: all 16 steps read only OLD values -> no serial predicate
// chain. Semantics identical to sequential shift-insert with strict compares.
__device__ __forceinline__ void topk_insert(float (&hd)[KNN], int (&hi)[KNN],
                                            float d2, int idx)
{
    bool P[KNN];
#pragma unroll
    for (int s = 0; s < KNN; ++s) P[s] = (hd[s] > d2);
#pragma unroll
    for (int s = KNN-1; s >= 1; --s) {
        float nd = P[s] ? d2 : hd[s];
        int   ni = P[s] ? idx : hi[s];
        hd[s] = P[s-1] ? hd[s-1] : nd;
        hi[s] = P[s-1] ? hi[s-1] : ni;
    }
    if (P[0]) { hd[0] = d2; hi[0] = idx; }
}

// unsplit kNN (stage 1: 4096 queries vs 4096 sources; writes final idx)
template<int NSRC>
__global__ __launch_bounds__(256)
void knn_kernel(const float* __restrict__ cq, const float* __restrict__ ck,
                int Q, int* __restrict__ outidx)
{
    __shared__ float4 tile[1024];
    int b = blockIdx.y;
    int q = blockIdx.x*256 + threadIdx.x;
    const float* qp = cq + ((size_t)b*Q + q)*3;
    float qx = qp[0], qy = qp[1], qz = qp[2];
    float qn = qx*qx + qy*qy + qz*qz;
    float hd[KNN]; int hi[KNN];
#pragma unroll
    for (int k = 0; k < KNN; ++k) { hd[k] = 3.4e38f; hi[k] = 0; }

#pragma unroll 1
    for (int t0 = 0; t0 < NSRC; t0 += 1024) {
        __syncthreads();
        for (int i = threadIdx.x; i < 1024; i += 256) {
            const float* p = ck + ((size_t)b*NSRC + t0 + i)*3;
            float px = p[0], py = p[1], pz = p[2];
            tile[i] = make_float4(px, py, pz, px*px + py*py + pz*pz);
        }
        __syncthreads();
#pragma unroll 4
        for (int j = 0; j < 1024; ++j) {
            float4 p = tile[j];
            float dot = fmaf(qz, p.z, fmaf(qy, p.y, qx*p.x));
            float d2  = (qn - 2.0f*dot) + p.w;
            if (d2 < hd[KNN-1]) topk_insert(hd, hi, d2, t0 + j);
        }
    }
    int* op = outidx + ((size_t)b*Q + q)*KNN;
#pragma unroll
    for (int k = 0; k < KNN; ++k) op[k] = hi[k];
}

// source-chunked kNN: each block handles one chunk of sources, exact per-chunk top-16
template<int CHUNK>
__global__ __launch_bounds__(256)
void knn_chunk_kernel(const float* __restrict__ cq, const float* __restrict__ ck,
                      int Q, int NSRC, float* __restrict__ outd, int* __restrict__ outi)
{
    constexpr int TILE = (CHUNK < 1024) ? CHUNK : 1024;
    __shared__ float4 tile[TILE];
    int b = blockIdx.y, ch = blockIdx.z, nch = gridDim.z;
    int q = blockIdx.x*256 + threadIdx.x;
    int base = ch*CHUNK;
    const float* qp = cq + ((size_t)b*Q + q)*3;
    float qx = qp[0], qy = qp[1], qz = qp[2];
    float qn = qx*qx + qy*qy + qz*qz;
    float hd[KNN]; int hi[KNN];
#pragma unroll
    for (int k = 0; k < KNN; ++k) { hd[k] = 3.4e38f; hi[k] = 0; }

#pragma unroll 1
    for (int t0 = base; t0 < base + CHUNK; t0 += TILE) {
        __syncthreads();
        for (int i = threadIdx.x; i < TILE; i += 256) {
            const float* p = ck + ((size_t)b*NSRC + t0 + i)*3;
            float px = p[0], py = p[1], pz = p[2];
            tile[i] = make_float4(px, py, pz, px*px + py*py + pz*pz);
        }
        __syncthreads();
#pragma unroll 4
        for (int j = 0; j < TILE; ++j) {
            float4 p = tile[j];
            float dot = fmaf(qz, p.z, fmaf(qy, p.y, qx*p.x));
            float d2  = (qn - 2.0f*dot) + p.w;
            if (d2 < hd[KNN-1]) topk_insert(hd, hi, d2, t0 + j);
        }
    }
    size_t o = ((size_t)(b*Q + q)*nch + ch)*KNN;
#pragma unroll
    for (int k = 0; k < KNN; ++k) { outd[o+k] = hd[k]; outi[o+k] = hi[k]; }
}

// exact stable NCH-way merge of per-chunk sorted top-16 lists -> global top-16
template<int NCH>
__global__ void knn_mergeN_kernel(const float* __restrict__ kd, const int* __restrict__ ki,
                                  int total, int* __restrict__ outidx)
{
    int t = blockIdx.x*256 + threadIdx.x;
    if (t >= total) return;
    const float* pd = kd + (size_t)t*NCH*KNN;
    const int*   pi = ki + (size_t)t*NCH*KNN;
    float h[NCH]; int hx[NCH]; int pp[NCH];
#pragma unroll
    for (int c = 0; c < NCH; ++c) { h[c] = pd[c*KNN]; hx[c] = pi[c*KNN]; pp[c] = 1; }
    const float INF = __int_as_float(0x7f800000);
    int* op = outidx + (size_t)t*KNN;
#pragma unroll
    for (int s = 0; s < KNN; ++s) {
        float bd = h[0]; int bi = hx[0]; int wc = 0;
#pragma unroll
        for (int c = 1; c < NCH; ++c) {
            if (h[c] < bd || (h[c] == bd && hx[c] < bi)) { bd = h[c]; bi = hx[c]; wc = c; }
        }
        op[s] = bi;
#pragma unroll
        for (int c = 0; c < NCH; ++c) {
            if (c == wc) {
                if (pp[c] < KNN) { h[c] = pd[c*KNN + pp[c]]; hx[c] = pi[c*KNN + pp[c]]; ++pp[c]; }
                else             { h[c] = INF; }
            }
        }
    }
}

// ---------------- farthest point sampling (exact argmax-first-tie) ----------------
// Packed f32x2 distance updates (identical per-component IEEE ops, same order),
// local-index-only argmax tracking, winner-lane coordinate select tree.
template<int N, int THREADS>
__global__ __launch_bounds__(THREADS)
void fps_kernel(const float* __restrict__ coor, int* __restrict__ out)
{
    constexpr int P  = N / THREADS;      // 4
    constexpr int P2 = P / 2;            // 2
    constexpr int NW = THREADS / 32;
    int b = blockIdx.x, tid = threadIdx.x;
    int lane = tid & 31, w = tid >> 5;
    const float* cb = coor + (size_t)b*N*3;
    unsigned long long px2[P2], py2[P2], pz2[P2], dist2[P2];
#pragma unroll
    for (int i2 = 0; i2 < P2; ++i2) {
        int p0 = tid*P + 2*i2, p1 = p0 + 1;
        px2[i2] = pk2(cb[p0*3+0], cb[p1*3+0]);
        py2[i2] = pk2(cb[p0*3+1], cb[p1*3+1]);
        pz2[i2] = pk2(cb[p0*3+2], cb[p1*3+2]);
        float inf = __int_as_float(0x7f800000);
        dist2[i2] = pk2(inf, inf);
    }
    __shared__ unsigned sD[2][NW]; __shared__ int sI[2][NW];
    __shared__ float sX[2][NW], sY[2][NW], sZ[2][NW];
    if (tid == 0) out[b*QPTS + 0] = 0;
    float cx = cb[0], cy = cb[1], cz = cb[2];

#pragma unroll 1
    for (int it = 1; it < QPTS; ++it) {
        int par = it & 1;
        unsigned long long ncx2 = pk2(-cx, -cx);
        unsigned long long ncy2 = pk2(-cy, -cy);
        unsigned long long ncz2 = pk2(-cz, -cz);
        float bd = -1.0f; int li = 0;
#pragma unroll
        for (int i2 = 0; i2 < P2; ++i2) {
            // per-component: dx = px + (-cx) == px - cx (exact)
            unsigned long long dx2 = add2p(px2[i2], ncx2);
            unsigned long long dy2 = add2p(py2[i2], ncy2);
            unsigned long long dz2 = add2p(pz2[i2], ncz2);
            // d = ((dx*dx + dy*dy) + dz*dz), each step rn, no fma fusion
            unsigned long long s2 = add2p(add2p(mul2p(dx2,dx2), mul2p(dy2,dy2)),
                                          mul2p(dz2,dz2));
            float d0 = fminf(lo2(dist2[i2]), lo2(s2));
            float d1 = fminf(hi2(dist2[i2]), hi2(s2));
            dist2[i2] = pk2(d0, d1);
            if (d0 > bd) { bd = d0; li = 2*i2; }      // ascending: first-max
            if (d1 > bd) { bd = d1; li = 2*i2 + 1; }
        }
        unsigned db   = __float_as_uint(bd);
        unsigned wmax = __reduce_max_sync(0xffffffffu, db);
        unsigned msk  = __ballot_sync(0xffffffffu, db == wmax);
        int src = __ffs(msk) - 1;                // lowest lane = lowest index
        if (lane == src) {
            // reconstruct winner coords from own registers (tiny select tree)
            unsigned long long sx = (li >> 1) ? px2[P2-1] : px2[0];
            unsigned long long sy = (li >> 1) ? py2[P2-1] : py2[0];
            unsigned long long sz = (li >> 1) ? pz2[P2-1] : pz2[0];
            float bx = (li & 1) ? hi2(sx) : lo2(sx);
            float by = (li & 1) ? hi2(sy) : lo2(sy);
            float bz = (li & 1) ? hi2(sz) : lo2(sz);
            sD[par][w] = wmax; sI[par][w] = tid*P + li;
            sX[par][w] = bx;   sY[par][w] = by;  sZ[par][w] = bz;
        }
        __syncthreads();
        unsigned slotd = sD[par][lane & (NW-1)];
        unsigned gmax = __reduce_max_sync(0xffffffffu, slotd);
        unsigned m2   = __ballot_sync(0xffffffffu, slotd == gmax);
        int w2 = __ffs(m2) - 1;                  // lowest warp = lowest index
        if (tid == 0) out[b*QPTS + it] = sI[par][w2];
        cx = sX[par][w2]; cy = sY[par][w2]; cz = sZ[par][w2];   // LDS broadcast
    }
}

// ---------------- fused edge-conv: packed f32x2 GEMM + max/min + GN partials ----------
template<int C, int CO>
__global__ __launch_bounds__(256)
void conv_kernel(const float* __restrict__ fsrc, const float* __restrict__ fq,
                 const int* __restrict__ knnidx, const float* __restrict__ W,
                 float* __restrict__ vmax, float* __restrict__ vmin,
                 float* __restrict__ part, int Q, int NSRC)
{
    constexpr int C2 = 2*C, CT = CO/16, CT2 = CT/2, NCH = C2/16;
    extern __shared__ float smem[];
    int*   sNb  = (int*)smem;
    float* sFq  = smem + 128;
    float* sNbF = sFq + 8*C;
    float* sW   = sNbF + 128*C;

    int b = blockIdx.y, blk = blockIdx.x, qbase = blk*8;
    int tid = threadIdx.x;
    int ty = tid >> 4, tx = tid & 15;
    int lane = tid & 31, w = tid >> 5;

    if (tid < 128) sNb[tid] = knnidx[((size_t)(b*Q + qbase))*KNN + tid];
    for (int e = tid; e < 8*C; e += 256) {
        int r = e / C, c = e % C;
        sFq[e] = fq[((size_t)(b*Q + qbase + r))*C + c];
    }
    __syncthreads();
    for (int v = tid; v < 128*(C/4); v += 256) {
        int row = v / (C/4), c4 = v % (C/4);
        float4 t = *reinterpret_cast<const float4*>(
            fsrc + ((size_t)(b*NSRC) + sNb[row])*C + c4*4);
        float* d = sNbF + row*C + c4*4;
        d[0] = t.x; d[1] = t.y; d[2] = t.z; d[3] = t.w;
    }
    unsigned long long acc2[8][CT2];
#pragma unroll
    for (int r = 0; r < 8; ++r)
#pragma unroll
        for (int i = 0; i < CT2; ++i) acc2[r][i] = 0ull;
    __syncthreads();

#pragma unroll 1
    for (int ch = 0; ch < NCH; ++ch) {
        for (int e = tid; e < 16*CO; e += 256) {
            int o = e % CO, j = e / CO;
            sW[j*CO + o] = W[(size_t)o*C2 + ch*16 + j];
        }
        __syncthreads();
#pragma unroll
        for (int j = 0; j < 16; ++j) {
            int c2 = ch*16 + j;
            unsigned long long wp[CT2];
            const unsigned long long* ws =
                reinterpret_cast<const unsigned long long*>(sW + j*CO + tx*CT);
#pragma unroll
            for (int i = 0; i < CT2; ++i) wp[i] = ws[i];
#pragma unroll
            for (int r = 0; r < 8; ++r) {
                int row = ty*8 + r, ql = row >> 4;
                float ev = (c2 < C) ? (sNbF[row*C + c2] - sFq[ql*C + c2])
                                    : sFq[ql*C + (c2 - C)];
                unsigned long long evev;
                asm("mov.b64 %0, {%1, %1};" : "=l"(evev) : "f"(ev));
#pragma unroll
                for (int i = 0; i < CT2; ++i)
                    asm("fma.rn.f32x2 %0, %1, %2, %0;"
                        : "+l"(acc2[r][i]) : "l"(evev), "l"(wp[i]));
            }
        }
        __syncthreads();
    }

    // phase 2 (registers): max/min over this thread's 8 rows per channel pair,
    // combine ty-pair via shfl_xor(16) -> full 16-k reduction for query w.
    int khalf = ty & 1;
    float s = 0.0f, ss = 0.0f;
    size_t obase = ((size_t)(b*Q + qbase + w))*CO + tx*CT;
#pragma unroll
    for (int i2 = 0; i2 < CT2; ++i2) {
        float mx0 = -3.4e38f, mn0 = 3.4e38f, mx1 = -3.4e38f, mn1 = 3.4e38f;
#pragma unroll
        for (int r = 0; r < 8; ++r) {
            unsigned long long a = acc2[r][i2];
            float v0 = __uint_as_float((unsigned)a);
            float v1 = __uint_as_float((unsigned)(a >> 32));
            mx0 = fmaxf(mx0, v0); mn0 = fminf(mn0, v0);
            mx1 = fmaxf(mx1, v1); mn1 = fminf(mn1, v1);
            s += v0; ss = fmaf(v0, v0, ss);
            s += v1; ss = fmaf(v1, v1, ss);
        }
        mx0 = fmaxf(mx0, __shfl_xor_sync(0xffffffffu, mx0, 16));
        mn0 = fminf(mn0, __shfl_xor_sync(0xffffffffu, mn0, 16));
        mx1 = fmaxf(mx1, __shfl_xor_sync(0xffffffffu, mx1, 16));
        mn1 = fminf(mn1, __shfl_xor_sync(0xffffffffu, mn1, 16));
        if (khalf == 0) {
            vmax[obase + 2*i2]   = mx0; vmin[obase + 2*i2]   = mn0;
            vmax[obase + 2*i2+1] = mx1; vmin[obase + 2*i2+1] = mn1;
        }
    }
    // segmented group sums: group g = tx>>2 ; combine ty pair + tx quad
    s  += __shfl_xor_sync(0xffffffffu, s, 16);
    ss += __shfl_xor_sync(0xffffffffu, ss, 16);
    s  += __shfl_xor_sync(0xffffffffu, s, 1);
    ss += __shfl_xor_sync(0xffffffffu, ss, 1);
    s  += __shfl_xor_sync(0xffffffffu, s, 2);
    ss += __shfl_xor_sync(0xffffffffu, ss, 2);
    float* sGs  = smem;        // safe: barrier above, phase-1 buffers dead
    float* sGss = smem + 32;
    if ((lane & 16) == 0 && (lane & 3) == 0) {
        int slot = w*4 + (lane >> 2);
        sGs[slot] = s; sGss[slot] = ss;
    }
    __syncthreads();
    if (tid < 4) {
        float gs = 0.0f, gss = 0.0f;
#pragma unroll
        for (int ww = 0; ww < 8; ++ww) { gs += sGs[ww*4 + tid]; gss += sGss[ww*4 + tid]; }
        float* p = part + ((size_t)b*gridDim.x + blk)*8;
        p[tid*2] = gs; p[tid*2+1] = gss;
    }
}

// ---------------- GN statistics (deterministic fixed-order) ----------------
__global__ void stats_kernel(const float* __restrict__ part, int NB, float invcnt,
                             float* __restrict__ mean, float* __restrict__ rs)
{
    int bg = blockIdx.x;            // b*4+g
    int b = bg >> 2, g = bg & 3;
    float s = 0.0f, ss = 0.0f;
    for (int i = threadIdx.x; i < NB; i += 32) {
        const float* p = part + ((size_t)b*NB + i)*8 + g*2;
        s += p[0]; ss += p[1];
    }
#pragma unroll
    for (int off = 16; off; off >>= 1) {
        s  += __shfl_down_sync(0xffffffffu, s,  off);
        ss += __shfl_down_sync(0xffffffffu, ss, off);
    }
    if (threadIdx.x == 0) {
        float m = s * invcnt;
        float var = ss * invcnt - m*m;
        mean[bg] = m;
        rs[bg] = 1.0f / sqrtf(var + 1e-5f);
    }
}

// ---------------- apply GN + affine + LeakyReLU on the extremum ----------------
__global__ void apply_kernel(const float* __restrict__ vmax, const float* __restrict__ vmin,
                             const float* __restrict__ mean, const float* __restrict__ rs,
                             const float* __restrict__ gw, const float* __restrict__ gb,
                             float* __restrict__ dst, int Q, int CO)
{
    int idx = blockIdx.x*256 + threadIdx.x;
    if (idx >= BATCH*Q*CO) return;
    int c = idx % CO;
    int b = idx / (Q*CO);
    int g = c / (CO >> 2);
    float gwc = gw[c];
    float v = (gwc >= 0.0f) ? vmax[idx] : vmin[idx];
    float y = fmaf((v - mean[b*4+g]) * rs[b*4+g], gwc, gb[c]);
    dst[idx] = (y > 0.0f) ? y : 0.2f*y;
}

// ---------------- gathers ----------------
__global__ void gather1_kernel(const float* __restrict__ x, const float* __restrict__ f1,
                               const int* __restrict__ idx,
                               float* __restrict__ coorq, float* __restrict__ nrm,
                               float* __restrict__ pln, float* __restrict__ fq)
{
    int t = blockIdx.x*256 + threadIdx.x;
    if (t >= BATCH*QPTS) return;
    int b = t >> 10;
    int i = idx[t];
    const float* xs = x + ((size_t)b*NPTS + i)*7;
    coorq[t*3+0] = xs[0]; coorq[t*3+1] = xs[1]; coorq[t*3+2] = xs[2];
    nrm[t*3+0] = xs[3]; nrm[t*3+1] = xs[4]; nrm[t*3+2] = xs[5];
    pln[t] = xs[6];
    const float4* fs = (const float4*)(f1 + ((size_t)b*NPTS + i)*32);
    float4* fd = (float4*)(fq + (size_t)t*32);
#pragma unroll
    for (int j = 0; j < 8; ++j) fd[j] = fs[j];
}

__global__ void gather2_kernel(const float* __restrict__ coorq, const float* __restrict__ nrm1,
                               const float* __restrict__ pln1, const float* __restrict__ f3,
                               const int* __restrict__ idx,
                               float* __restrict__ out, float* __restrict__ fq2)
{
    int t = blockIdx.x*256 + threadIdx.x;
    if (t >= BATCH*QPTS) return;
    int b = t >> 10;
    int i = idx[t];
    size_t src = (size_t)b*QPTS + i;
    out[OUT_COOR + t*3+0] = coorq[src*3+0];
    out[OUT_COOR + t*3+1] = coorq[src*3+1];
    out[OUT_COOR + t*3+2] = coorq[src*3+2];
    out[OUT_NRM + t*3+0] = nrm1[src*3+0];
    out[OUT_NRM + t*3+1] = nrm1[src*3+1];
    out[OUT_NRM + t*3+2] = nrm1[src*3+2];
    out[OUT_PLN + t] = pln1[src];
    const float4* fs = (const float4*)(f3 + src*64);
    float4* fd = (float4*)(fq2 + (size_t)t*64);
#pragma unroll
    for (int j = 0; j < 16; ++j) fd[j] = fs[j];
}

// ---------------- host ----------------
static int conv_smem(int C, int CO) {
    return 4 * (128 + 8*C + 128*C + 16*CO);
}

static cudaStream_t s_side = 0;
static cudaEvent_t  s_evF1, s_evJ1, s_evF2, s_evJ2;

extern "C" void kernel_launch(void* const* d_in, const int* in_sizes, int n_in,
                              void* d_out, int out_size)
{
    const float* x   = (const float*)d_in[0];
    const float* Win = (const float*)d_in[1];
    const float* bin = (const float*)d_in[2];
    const float* W1  = (const float*)d_in[3];
    const float* g1w = (const float*)d_in[4];
    const float* g1b = (const float*)d_in[5];
    const float* W2  = (const float*)d_in[6];
    const float* g2w = (const float*)d_in[7];
    const float* g2b = (const float*)d_in[8];
    const float* W3  = (const float*)d_in[9];
    const float* g3w = (const float*)d_in[10];
    const float* g3b = (const float*)d_in[11];
    const float* W4  = (const float*)d_in[12];
    const float* g4w = (const float*)d_in[13];
    const float* g4b = (const float*)d_in[14];
    float* out = (float*)d_out;

    if (!s_side) {
        cudaStreamCreateWithFlags(&s_side, cudaStreamNonBlocking);
        cudaEventCreateWithFlags(&s_evF1, cudaEventDisableTiming);
        cudaEventCreateWithFlags(&s_evJ1, cudaEventDisableTiming);
        cudaEventCreateWithFlags(&s_evF2, cudaEventDisableTiming);
        cudaEventCreateWithFlags(&s_evJ2, cudaEventDisableTiming);
    }

    float *coor, *f0, *f1, *f2, *f3, *fq1, *fq2, *coorq, *nrm1, *pln1;
    float *vmax, *vmin, *part, *mean, *rs, *kd;
    int *knn, *fps1, *fps2, *ki;
    cudaGetSymbolAddress((void**)&coor,  g_coor);
    cudaGetSymbolAddress((void**)&f0,    g_f0);
    cudaGetSymbolAddress((void**)&f1,    g_f1);
    cudaGetSymbolAddress((void**)&f2,    g_f2);
    cudaGetSymbolAddress((void**)&f3,    g_f3);
    cudaGetSymbolAddress((void**)&fq1,   g_fq1);
    cudaGetSymbolAddress((void**)&fq2,   g_fq2);
    cudaGetSymbolAddress((void**)&coorq, g_coorq);
    cudaGetSymbolAddress((void**)&nrm1,  g_nrm1);
    cudaGetSymbolAddress((void**)&pln1,  g_pln1);
    cudaGetSymbolAddress((void**)&vmax,  g_vmax);
    cudaGetSymbolAddress((void**)&vmin,  g_vmin);
    cudaGetSymbolAddress((void**)&part,  g_part);
    cudaGetSymbolAddress((void**)&mean,  g_mean);
    cudaGetSymbolAddress((void**)&rs,    g_rs);
    cudaGetSymbolAddress((void**)&kd,    g_kd);
    cudaGetSymbolAddress((void**)&ki,    g_ki);
    cudaGetSymbolAddress((void**)&knn,   g_knn);
    cudaGetSymbolAddress((void**)&fps1,  g_fps1);
    cudaGetSymbolAddress((void**)&fps2,  g_fps2);

    cudaFuncSetAttribute(conv_kernel<8,32>,   cudaFuncAttributeMaxDynamicSharedMemorySize, conv_smem(8,32));
    cudaFuncSetAttribute(conv_kernel<32,64>,  cudaFuncAttributeMaxDynamicSharedMemorySize, conv_smem(32,64));
    cudaFuncSetAttribute(conv_kernel<64,64>,  cudaFuncAttributeMaxDynamicSharedMemorySize, conv_smem(64,64));
    cudaFuncSetAttribute(conv_kernel<64,128>, cudaFuncAttributeMaxDynamicSharedMemorySize, conv_smem(64,128));

    // stage 0
    init_kernel<<<(BATCH*NPTS+255)/256, 256>>>(x, Win, bin, coor, f0);

    // fork: FPS level 1 on side stream (only needs coor; 8 blocks, near-free overlap)
    cudaEventRecord(s_evF1, 0);
    cudaStreamWaitEvent(s_side, s_evF1, 0);
    fps_kernel<NPTS,1024><<<BATCH, 1024, 0, s_side>>>(coor, fps1);
    cudaEventRecord(s_evJ1, s_side);

    // stage 1 (overlaps FPS1): knn(4096 vs 4096), conv C=8 CO=32
    knn_kernel<NPTS><<<dim3(NPTS/256, BATCH), 256>>>(coor, coor, NPTS, knn);
    conv_kernel<8,32><<<dim3(NPTS/8, BATCH), 256, conv_smem(8,32)>>>(
        f0, f0, knn, W1, vmax, vmin, part, NPTS, NPTS);
    stats_kernel<<<BATCH*4, 32>>>(part, NPTS/8, 1.0f/(NPTS*16*8), mean, rs);
    apply_kernel<<<(BATCH*NPTS*32+255)/256, 256>>>(vmax, vmin, mean, rs, g1w, g1b, f1, NPTS, 32);

    // join FPS1, gather
    cudaStreamWaitEvent(0, s_evJ1, 0);
    gather1_kernel<<<(BATCH*QPTS+255)/256, 256>>>(x, f1, fps1, coorq, nrm1, pln1, fq1);

    // fork: FPS level 2 on side stream (only needs coorq)
    cudaEventRecord(s_evF2, 0);
    cudaStreamWaitEvent(s_side, s_evF2, 0);
    fps_kernel<QPTS,256><<<BATCH, 256, 0, s_side>>>(coorq, fps2);
    cudaEventRecord(s_evJ2, s_side);

    // stage 2 (overlaps FPS2): 4-chunk knn(1024 q vs 4096 src), conv C=32 CO=64
    knn_chunk_kernel<1024><<<dim3(QPTS/256, BATCH, 4), 256>>>(coorq, coor, QPTS, NPTS, kd, ki);
    knn_mergeN_kernel<4><<<(BATCH*QPTS+255)/256, 256>>>(kd, ki, BATCH*QPTS, knn);
    conv_kernel<32,64><<<dim3(QPTS/8, BATCH), 256, conv_smem(32,64)>>>(
        f1, fq1, knn, W2, vmax, vmin, part, QPTS, NPTS);
    stats_kernel<<<BATCH*4, 32>>>(part, QPTS/8, 1.0f/(QPTS*16*16), mean, rs);
    apply_kernel<<<(BATCH*QPTS*64+255)/256, 256>>>(vmax, vmin, mean, rs, g2w, g2b, f2, QPTS, 64);

    // stage 3 (overlaps FPS2): 4-chunk knn(1024 vs 1024), conv C=64 CO=64
    knn_chunk_kernel<256><<<dim3(QPTS/256, BATCH, 4), 256>>>(coorq, coorq, QPTS, QPTS, kd, ki);
    knn_mergeN_kernel<4><<<(BATCH*QPTS+255)/256, 256>>>(kd, ki, BATCH*QPTS, knn);
    conv_kernel<64,64><<<dim3(QPTS/8, BATCH), 256, conv_smem(64,64)>>>(
        f2, f2, knn, W3, vmax, vmin, part, QPTS, QPTS);
    stats_kernel<<<BATCH*4, 32>>>(part, QPTS/8, 1.0f/(QPTS*16*16), mean, rs);
    apply_kernel<<<(BATCH*QPTS*64+255)/256, 256>>>(vmax, vmin, mean, rs, g3w, g3b, f3, QPTS, 64);

    // join FPS2, gather (writes coor_q/normal_q/plane_q straight to output)
    cudaStreamWaitEvent(0, s_evJ2, 0);
    gather2_kernel<<<(BATCH*QPTS+255)/256, 256>>>(coorq, nrm1, pln1, f3, fps2, out, fq2);

    // stage 4: 4-chunk knn(permuted 1024 vs 1024), conv C=64 CO=128 -> final f into output
    knn_chunk_kernel<256><<<dim3(QPTS/256, BATCH, 4), 256>>>(out + OUT_COOR, coorq, QPTS, QPTS, kd, ki);
    knn_mergeN_kernel<4><<<(BATCH*QPTS+255)/256, 256>>>(kd, ki, BATCH*QPTS, knn);
    conv_kernel<64,128><<<dim3(QPTS/8, BATCH), 256, conv_smem(64,128)>>>(
        f3, fq2, knn, W4, vmax, vmin, part, QPTS, QPTS);
    stats_kernel<<<BATCH*4, 32>>>(part, QPTS/8, 1.0f/(QPTS*16*32), mean, rs);
    apply_kernel<<<(BATCH*QPTS*128+255)/256, 256>>>(vmax, vmin, mean, rs, g4w, g4b,
                                                    out + OUT_F, QPTS, 128);
}